// round 1
// baseline (speedup 1.0000x reference)
#include <cuda_runtime.h>
#include <cuda_bf16.h>
#include <math.h>

// Phase 2: deterministic winner election via atomicMax of pair index.
// d_out was memset to 0; pair indices are >= 0, so max() over {0, winners}
// is well-defined. Pair 0 "wins" iff nothing larger touched its cell, and
// the untouched-cell value (0) coincides with pair index 0 harmlessly:
// phase 3 only checks cells that some pair actually touches.
__global__ void se_elect_kernel(const int* __restrict__ src,
                                const int* __restrict__ dst,
                                int n_pairs, int nn,
                                int* __restrict__ out_i) {
    int i = blockIdx.x * blockDim.x + threadIdx.x;
    if (i >= n_pairs) return;
    long long cell = (long long)src[i] * nn + dst[i];
    atomicMax(&out_i[cell], i);
}

// Phase 3: winner writes its float value. Each cell has exactly one winner,
// so plain stores, no races. Non-touched cells keep int 0 == float 0.0f bits.
__global__ void se_write_kernel(const float* __restrict__ b,
                                const int* __restrict__ src,
                                const int* __restrict__ dst,
                                const int* __restrict__ path_len,
                                int n_pairs, int nn, int max_path,
                                const int* __restrict__ out_i,
                                float* __restrict__ out_f) {
    int i = blockIdx.x * blockDim.x + threadIdx.x;
    if (i >= n_pairs) return;
    long long cell = (long long)src[i] * nn + dst[i];
    if (out_i[cell] == i) {
        int pl = path_len[i];
        int bucket = (pl < max_path ? pl : max_path) - 1;
        if (bucket < 0) bucket = 0;
        if (bucket > max_path - 1) bucket = max_path - 1;
        out_f[cell] = b[bucket];
    }
}

extern "C" void kernel_launch(void* const* d_in, const int* in_sizes, int n_in,
                              void* d_out, int out_size) {
    // metadata order: x [n_nodes, 128] f32, b [max_path] f32,
    //                 src [n_pairs] i32, dst [n_pairs] i32, path_len [n_pairs] i32
    const float* b        = (const float*)d_in[1];
    const int*   src      = (const int*)d_in[2];
    const int*   dst      = (const int*)d_in[3];
    const int*   path_len = (const int*)d_in[4];

    int max_path = in_sizes[1];
    int n_pairs  = in_sizes[2];
    // out is [nn, nn]; derive nn robustly from out_size
    int nn = (int)(sqrt((double)out_size) + 0.5);

    float* out_f = (float*)d_out;
    int*   out_i = (int*)d_out;

    // Phase 1: mandatory 256MB zero-fill at memset bandwidth (graph-capturable).
    cudaMemsetAsync(d_out, 0, (size_t)out_size * sizeof(float), 0);

    const int T = 256;
    int blocks = (n_pairs + T - 1) / T;

    // Phase 2: elect last-pair-index winner per cell (deterministic).
    se_elect_kernel<<<blocks, T>>>(src, dst, n_pairs, nn, out_i);

    // Phase 3: winners write the bias value.
    se_write_kernel<<<blocks, T>>>(b, src, dst, path_len, n_pairs, nn,
                                   max_path, out_i, out_f);
}